// round 14
// baseline (speedup 1.0000x reference)
#include <cuda_runtime.h>
#include <cuda_fp16.h>
#include <mma.h>

using namespace nvcuda;

#define NEG 0.2f
#define MAXN 100000
#define MAXE 1600000
#define MAXET (MAXN + MAXE)

// ---------------- scratch ----------------------------------------------------
__device__ int     g_csrc[MAXET];              // CSR column (src) indices
__device__ int     g_deg[MAXN];
__device__ int     g_rowptr[MAXN];
__device__ int     g_wp[MAXN];
__device__ int     g_total;
__device__ __half2 g_h1h[(size_t)MAXN * 64];   // h1 as fp16 (gather payload)
__device__ float   g_x2 [(size_t)MAXN * 128];  // relu(agg1+b1): layer-2 input
__device__ float   g_als1[MAXN * 4];
__device__ float   g_ald1[MAXN * 4];
__device__ __half2 g_h2h[MAXN * 8];            // h2 as fp16
__device__ float   g_als2[MAXN];
__device__ float   g_ald2[MAXN];

// ---------------- helpers ----------------------------------------------------
__device__ __forceinline__ float lexp(float e) {
    e = e > 0.f ? e : NEG * e;            // LeakyReLU(0.2)
    return __expf(e);                     // softmax shift-invariant: no max pass
}

// ---------------- k_zero ------------------------------------------------------
__global__ void k_zero(int N) {
    int i = blockIdx.x * blockDim.x + threadIdx.x;
    if (i < N) g_deg[i] = 0;
    if (i == 0) g_total = 0;
}

// ---------------- k_hist: degree histogram (incl. self loops) ----------------
__global__ void k_hist(const int* __restrict__ ei, int E, int ET) {
    int i = blockIdx.x * blockDim.x + threadIdx.x;
    if (i >= ET) return;
    int d = (i < E) ? ei[E + i] : (i - E);
    atomicAdd(&g_deg[d], 1);
}

// ---------------- k_offsets: segment offsets via atomic bump -----------------
__global__ void k_offsets(int N) {
    int i = blockIdx.x * blockDim.x + threadIdx.x;
    if (i >= N) return;
    int d = g_deg[i];
    int off = atomicAdd(&g_total, d);
    g_rowptr[i] = off;
    g_wp[i] = off;
}

// ---------------- k_scatter: build CSR from ei --------------------------------
__global__ void k_scatter(const int* __restrict__ ei, int E, int ET) {
    int i = blockIdx.x * blockDim.x + threadIdx.x;
    if (i >= ET) return;
    int s, d;
    if (i < E) { s = ei[i]; d = ei[E + i]; }
    else       { s = d = i - E; }
    int pos = atomicAdd(&g_wp[d], 1);
    g_csrc[pos] = s;
}

// ---------------- k_gemm1h: x@W1 via fp16 wmma + attention logits ------------
// Tile: 64 rows x 128 cols, 8 warps = 4(M) x 2(N), m16n16k16, fp32 accum.
// Dynamic smem: Xs(64x136 half, 17408B) + Ws(128x136 half, 34816B) = 52224B.
// After MMA, region is reused as Cs(64x136 float, 34816B) for the epilogue.
#define GM_ROWS 64
#define LDH 136                           // padded half stride (mult of 8)
#define GSMEM (64 * LDH * 2 + 128 * LDH * 2)
__global__ void __launch_bounds__(256)
k_gemm1h(const float* __restrict__ x, const float* __restrict__ W1,
         const float* __restrict__ a_src1, const float* __restrict__ a_dst1,
         int n) {
    extern __shared__ char smraw[];
    __half* Xs = (__half*)smraw;                       // [64][LDH]
    __half* Ws = (__half*)(smraw + 64 * LDH * 2);      // [128][LDH]
    float*  Cs = (float*)smraw;                        // [64][LDH] (aliases)
    __shared__ float s_as[128], s_ad[128];
    __shared__ float s_als[GM_ROWS][4], s_ald[GM_ROWS][4];

    int t = threadIdx.x;
    int row0 = blockIdx.x * GM_ROWS;

    // fill tiles (fp32 -> fp16 on the fly)
    for (int i = t; i < 128 * 128; i += 256) {
        int r = i >> 7, c = i & 127;
        Ws[r * LDH + c] = __float2half(W1[i]);
    }
    for (int i = t; i < GM_ROWS * 128; i += 256) {
        int r = i >> 7, c = i & 127;
        int row = row0 + r;
        Xs[r * LDH + c] = (row < n) ? __float2half(x[(size_t)row * 128 + c])
                                    : __float2half(0.f);
    }
    if (t < 128) { s_as[t] = a_src1[t]; s_ad[t] = a_dst1[t]; }
    if (t < GM_ROWS * 4) { ((float*)s_als)[t] = 0.f; ((float*)s_ald)[t] = 0.f; }
    __syncthreads();

    // MMA: warp (mi, ni) computes rows mi*16..+16, cols ni*64..+64
    {
        int wid = t >> 5;
        int mi = wid & 3, ni = wid >> 2;
        wmma::fragment<wmma::accumulator, 16, 16, 16, float> acc[4];
#pragma unroll
        for (int nn = 0; nn < 4; nn++) wmma::fill_fragment(acc[nn], 0.f);

#pragma unroll
        for (int k = 0; k < 8; k++) {
            wmma::fragment<wmma::matrix_a, 16, 16, 16, __half, wmma::row_major> af;
            wmma::load_matrix_sync(af, Xs + (mi * 16) * LDH + k * 16, LDH);
#pragma unroll
            for (int nn = 0; nn < 4; nn++) {
                wmma::fragment<wmma::matrix_b, 16, 16, 16, __half, wmma::row_major> bf;
                wmma::load_matrix_sync(bf, Ws + (k * 16) * LDH + ni * 64 + nn * 16, LDH);
                wmma::mma_sync(acc[nn], af, bf, acc[nn]);
            }
        }
        __syncthreads();   // all warps done reading Xs/Ws before aliasing as Cs
#pragma unroll
        for (int nn = 0; nn < 4; nn++)
            wmma::store_matrix_sync(Cs + (mi * 16) * LDH + ni * 64 + nn * 16,
                                    acc[nn], LDH, wmma::mem_row_major);
    }
    __syncthreads();

    // epilogue: h1h store + attention logits (identical math to fp32 version)
    const int c0 = (t & 31) * 4;
    const int r0 = (t >> 5) * 8;
    const int head = c0 >> 5;
#pragma unroll
    for (int r = 0; r < 8; r++) {
        int rr = r0 + r;
        int row = row0 + rr;
        if (row < n) {
            float4 v = *(const float4*)&Cs[rr * LDH + c0];
            __half2 p0 = __floats2half2_rn(v.x, v.y);
            __half2 p1 = __floats2half2_rn(v.z, v.w);
            uint2 pk;
            pk.x = *(unsigned int*)&p0;
            pk.y = *(unsigned int*)&p1;
            *(uint2*)&g_h1h[(size_t)row * 64 + (c0 >> 1)] = pk;
            float ps = v.x * s_as[c0]     + v.y * s_as[c0 + 1]
                     + v.z * s_as[c0 + 2] + v.w * s_as[c0 + 3];
            float pd = v.x * s_ad[c0]     + v.y * s_ad[c0 + 1]
                     + v.z * s_ad[c0 + 2] + v.w * s_ad[c0 + 3];
            atomicAdd(&s_als[rr][head], ps);
            atomicAdd(&s_ald[rr][head], pd);
        }
    }
    __syncthreads();
    if (t < GM_ROWS * 4) {
        int r = t >> 2, hh = t & 3;
        int row = row0 + r;
        if (row < n) {
            g_als1[row * 4 + hh] = s_als[r][hh];
            g_ald1[row * 4 + hh] = s_ald[r][hh];
        }
    }
}

// ---------------- k_agg1: CSR warp-per-node aggregate (no atomics) -----------
__global__ void __launch_bounds__(256)
k_agg1(const float* __restrict__ b1, int N) {
    int node = (blockIdx.x * blockDim.x + threadIdx.x) >> 5;
    if (node >= N) return;
    int lane = threadIdx.x & 31;
    int h = lane >> 3;
    float ald = __ldg(&g_ald1[node * 4 + h]);
    int j   = g_rowptr[node];
    int end = j + g_deg[node];
    float4 acc = make_float4(0.f, 0.f, 0.f, 0.f);
    float den = 0.f;

    for (; j + 1 < end; j += 2) {
        int s0 = __ldg(&g_csrc[j]);
        int s1 = __ldg(&g_csrc[j + 1]);
        float w0 = lexp(__ldg(&g_als1[s0 * 4 + h]) + ald);
        float w1 = lexp(__ldg(&g_als1[s1 * 4 + h]) + ald);
        uint2 u0 = *(const uint2*)&g_h1h[(size_t)s0 * 64 + lane * 2];
        uint2 u1 = *(const uint2*)&g_h1h[(size_t)s1 * 64 + lane * 2];
        float2 a0 = __half22float2(*(__half2*)&u0.x);
        float2 a1 = __half22float2(*(__half2*)&u0.y);
        float2 c0 = __half22float2(*(__half2*)&u1.x);
        float2 c1 = __half22float2(*(__half2*)&u1.y);
        acc.x += w0 * a0.x + w1 * c0.x;
        acc.y += w0 * a0.y + w1 * c0.y;
        acc.z += w0 * a1.x + w1 * c1.x;
        acc.w += w0 * a1.y + w1 * c1.y;
        den   += w0 + w1;
    }
    if (j < end) {
        int s0 = __ldg(&g_csrc[j]);
        float w0 = lexp(__ldg(&g_als1[s0 * 4 + h]) + ald);
        uint2 u0 = *(const uint2*)&g_h1h[(size_t)s0 * 64 + lane * 2];
        float2 a0 = __half22float2(*(__half2*)&u0.x);
        float2 a1 = __half22float2(*(__half2*)&u0.y);
        acc.x += w0 * a0.x; acc.y += w0 * a0.y;
        acc.z += w0 * a1.x; acc.w += w0 * a1.y;
        den += w0;
    }

    float inv = __fdividef(1.f, den);
    float4 bb = *(const float4*)&b1[lane * 4];
    float4 o;
    o.x = fmaxf(acc.x * inv + bb.x, 0.f);
    o.y = fmaxf(acc.y * inv + bb.y, 0.f);
    o.z = fmaxf(acc.z * inv + bb.z, 0.f);
    o.w = fmaxf(acc.w * inv + bb.w, 0.f);
    *(float4*)&g_x2[(size_t)node * 128 + lane * 4] = o;
}

// ---------------- k_layer2: x2 @ W2 + layer-2 logits -------------------------
__global__ void __launch_bounds__(128)
k_layer2(const float* __restrict__ W2,
         const float* __restrict__ a_src2, const float* __restrict__ a_dst2,
         int n) {
    __shared__ float W2s[128 * 16];
    __shared__ float xs[8][128];
    __shared__ float outs[8][16];
    __shared__ float sa2[16], sd2[16];

    int t = threadIdx.x;
    int row0 = blockIdx.x * 8;

    for (int i = t; i < 128 * 16 / 4; i += 128)
        ((float4*)W2s)[i] = ((const float4*)W2)[i];
    if (t < 16) { sa2[t] = a_src2[t]; sd2[t] = a_dst2[t]; }
    __syncthreads();

    int nl = t >> 4, seg = t & 15;
    int row = row0 + nl;
    {
        int c = seg * 8;
#pragma unroll
        for (int jj = 0; jj < 2; jj++) {
            float4 v = (row < n)
                ? *(const float4*)&g_x2[(size_t)row * 128 + c + 4 * jj]
                : make_float4(0.f, 0.f, 0.f, 0.f);
            *(float4*)&xs[nl][c + 4 * jj] = v;
        }
    }
    __syncthreads();

    int o = seg;
    float acc = 0.f;
#pragma unroll 8
    for (int k = 0; k < 128; k += 4) {
        float4 xv = *(const float4*)&xs[nl][k];
        acc += xv.x * W2s[(k + 0) * 16 + o] + xv.y * W2s[(k + 1) * 16 + o]
             + xv.z * W2s[(k + 2) * 16 + o] + xv.w * W2s[(k + 3) * 16 + o];
    }
    outs[nl][o] = acc;
    // pack channel pair (o even) -> fp16x2 via shfl from o+1 (same node, same warp)
    float accn = __shfl_down_sync(0xffffffffu, acc, 1);
    if (!(o & 1) && row < n)
        g_h2h[row * 8 + (o >> 1)] = __floats2half2_rn(acc, accn);
    __syncthreads();

    if (o == 0 && row < n) {
        float ss = 0.f, sd = 0.f;
#pragma unroll
        for (int jj = 0; jj < 16; jj++) {
            ss += outs[nl][jj] * sa2[jj];
            sd += outs[nl][jj] * sd2[jj];
        }
        g_als2[row] = ss;
        g_ald2[row] = sd;
    }
}

// ---------------- k_agg2: CSR 8-thread-per-node aggregate into d_out ---------
__global__ void __launch_bounds__(256)
k_agg2(float* __restrict__ out, const float* __restrict__ b2, int N) {
    int g = blockIdx.x * blockDim.x + threadIdx.x;
    int node = g >> 3;
    if (node >= N) return;
    int c = g & 7;                         // channel pair index
    float ald = __ldg(&g_ald2[node]);
    int j   = g_rowptr[node];
    int end = j + g_deg[node];
    float ax = 0.f, ay = 0.f, den = 0.f;

    for (; j + 1 < end; j += 2) {
        int s0 = __ldg(&g_csrc[j]);
        int s1 = __ldg(&g_csrc[j + 1]);
        float w0 = lexp(__ldg(&g_als2[s0]) + ald);
        float w1 = lexp(__ldg(&g_als2[s1]) + ald);
        float2 f0 = __half22float2(g_h2h[s0 * 8 + c]);
        float2 f1 = __half22float2(g_h2h[s1 * 8 + c]);
        ax += w0 * f0.x + w1 * f1.x;
        ay += w0 * f0.y + w1 * f1.y;
        den += w0 + w1;
    }
    if (j < end) {
        int s0 = __ldg(&g_csrc[j]);
        float w0 = lexp(__ldg(&g_als2[s0]) + ald);
        float2 f0 = __half22float2(g_h2h[s0 * 8 + c]);
        ax += w0 * f0.x;
        ay += w0 * f0.y;
        den += w0;
    }

    float inv = __fdividef(1.f, den);
    float2 ov;
    ov.x = ax * inv + __ldg(&b2[2 * c]);
    ov.y = ay * inv + __ldg(&b2[2 * c + 1]);
    *(float2*)&out[node * 16 + 2 * c] = ov;
}

// ---------------- launch ------------------------------------------------------
extern "C" void kernel_launch(void* const* d_in, const int* in_sizes, int n_in,
                              void* d_out, int out_size) {
    const float* x      = (const float*)d_in[0];
    const int*   ei     = (const int*)d_in[1];     // JAX x64 off -> int32
    const float* W1     = (const float*)d_in[2];
    const float* a_src1 = (const float*)d_in[3];
    const float* a_dst1 = (const float*)d_in[4];
    const float* b1     = (const float*)d_in[5];
    const float* W2     = (const float*)d_in[6];
    const float* a_src2 = (const float*)d_in[7];
    const float* a_dst2 = (const float*)d_in[8];
    const float* b2     = (const float*)d_in[9];
    float* out = (float*)d_out;

    int N  = in_sizes[0] / 128;
    int E  = in_sizes[1] / 2;
    int ET = E + N;

    static int init_done = 0;
    if (!init_done) {
        cudaFuncSetAttribute(k_gemm1h, cudaFuncAttributeMaxDynamicSharedMemorySize,
                             GSMEM);
        init_done = 1;
    }

    k_zero<<<(N + 255) / 256, 256>>>(N);
    k_hist<<<(ET + 255) / 256, 256>>>(ei, E, ET);
    k_offsets<<<(N + 255) / 256, 256>>>(N);
    k_scatter<<<(ET + 255) / 256, 256>>>(ei, E, ET);

    k_gemm1h<<<(N + GM_ROWS - 1) / GM_ROWS, 256, GSMEM>>>(x, W1, a_src1, a_dst1, N);

    k_agg1<<<(N * 32 + 255) / 256, 256>>>(b1, N);
    k_layer2<<<(N + 7) / 8, 128>>>(W2, a_src2, a_dst2, N);
    k_agg2<<<(N * 8 + 255) / 256, 256>>>(out, b2, N);
}

// round 15
// speedup vs baseline: 1.4622x; 1.4622x over previous
#include <cuda_runtime.h>
#include <cuda_fp16.h>
#include <mma.h>

using namespace nvcuda;

#define NEG 0.2f
#define MAXN 100000
#define MAXE 1600000
#define MAXET (MAXN + MAXE)

// ---------------- scratch ----------------------------------------------------
__device__ int     g_csrc[MAXET];              // CSR column (src) indices
__device__ int     g_deg[MAXN];
__device__ int     g_rowptr[MAXN];
__device__ int     g_wp[MAXN];
__device__ int     g_total;
__device__ __half2 g_h1h[(size_t)MAXN * 64];   // h1 as fp16 (gather payload)
__device__ float   g_x2 [(size_t)MAXN * 128];  // relu(agg1+b1): layer-2 input
__device__ float   g_als1[MAXN * 4];
__device__ float   g_ald1[MAXN * 4];
__device__ __half2 g_h2h[MAXN * 8];            // h2 as fp16
__device__ float   g_als2[MAXN];
__device__ float   g_ald2[MAXN];

// ---------------- helpers ----------------------------------------------------
__device__ __forceinline__ float lexp(float e) {
    e = e > 0.f ? e : NEG * e;            // LeakyReLU(0.2)
    return __expf(e);                     // softmax shift-invariant: no max pass
}

// ---------------- k_zero ------------------------------------------------------
__global__ void k_zero(int N) {
    int i = blockIdx.x * blockDim.x + threadIdx.x;
    if (i < N) g_deg[i] = 0;
    if (i == 0) g_total = 0;
}

// ---------------- k_hist: degree histogram (incl. self loops) ----------------
__global__ void k_hist(const int* __restrict__ ei, int E, int ET) {
    int i = blockIdx.x * blockDim.x + threadIdx.x;
    if (i >= ET) return;
    int d = (i < E) ? ei[E + i] : (i - E);
    atomicAdd(&g_deg[d], 1);
}

// ---------------- k_offsets: segment offsets via atomic bump -----------------
__global__ void k_offsets(int N) {
    int i = blockIdx.x * blockDim.x + threadIdx.x;
    if (i >= N) return;
    int d = g_deg[i];
    int off = atomicAdd(&g_total, d);
    g_rowptr[i] = off;
    g_wp[i] = off;
}

// ---------------- k_scatter: build CSR from ei --------------------------------
__global__ void k_scatter(const int* __restrict__ ei, int E, int ET) {
    int i = blockIdx.x * blockDim.x + threadIdx.x;
    if (i >= ET) return;
    int s, d;
    if (i < E) { s = ei[i]; d = ei[E + i]; }
    else       { s = d = i - E; }
    int pos = atomicAdd(&g_wp[d], 1);
    g_csrc[pos] = s;
}

// ---------------- k_gemm1h: x@W1 via fp16 wmma + attention logits ------------
// v2: 128x128 tile per block (W1 converted once per 128 rows), vectorized
// float4->half2 fill, warp = 16-row strip x 128 cols (8 acc fragments).
// Dynamic smem: Xh[128][136] + Wh[128][136] halves = 69632B; epilogue aliases
// the same region as Cs[128][136] floats (exactly 69632B).
#define GM_ROWS 128
#define LDH 136                           // padded half stride
#define GSMEM (2 * 128 * LDH * 2)
__global__ void __launch_bounds__(256)
k_gemm1h(const float* __restrict__ x, const float* __restrict__ W1,
         const float* __restrict__ a_src1, const float* __restrict__ a_dst1,
         int n) {
    extern __shared__ char smraw[];
    __half* Xh = (__half*)smraw;                       // [128][LDH]
    __half* Wh = (__half*)(smraw + 128 * LDH * 2);     // [128][LDH]
    float*  Cs = (float*)smraw;                        // [128][LDH] (aliases)
    __shared__ float s_as[128], s_ad[128];
    __shared__ float s_als[GM_ROWS][4], s_ald[GM_ROWS][4];

    int t = threadIdx.x;
    int row0 = blockIdx.x * GM_ROWS;

    // vectorized fill: float4 load -> 2x half2 -> uint2 store (8B, conflict-free)
    for (int i = t; i < 128 * 32; i += 256) {          // W1: 128 rows x 32 quads
        int r = i >> 5, cq = i & 31;
        float4 v = ((const float4*)W1)[i];
        __half2 h0 = __floats2half2_rn(v.x, v.y);
        __half2 h1 = __floats2half2_rn(v.z, v.w);
        uint2 pk;
        pk.x = *(unsigned int*)&h0;
        pk.y = *(unsigned int*)&h1;
        *(uint2*)&Wh[r * LDH + cq * 4] = pk;
    }
    for (int i = t; i < GM_ROWS * 32; i += 256) {      // x tile
        int r = i >> 5, cq = i & 31;
        int row = row0 + r;
        float4 v = (row < n) ? ((const float4*)x)[(size_t)row * 32 + cq]
                             : make_float4(0.f, 0.f, 0.f, 0.f);
        __half2 h0 = __floats2half2_rn(v.x, v.y);
        __half2 h1 = __floats2half2_rn(v.z, v.w);
        uint2 pk;
        pk.x = *(unsigned int*)&h0;
        pk.y = *(unsigned int*)&h1;
        *(uint2*)&Xh[r * LDH + cq * 4] = pk;
    }
    if (t < 128) { s_as[t] = a_src1[t]; s_ad[t] = a_dst1[t]; }
    for (int i = t; i < GM_ROWS * 4; i += 256) {
        ((float*)s_als)[i] = 0.f;
        ((float*)s_ald)[i] = 0.f;
    }
    __syncthreads();

    // MMA: warp w computes rows w*16..+16, all 128 cols (8 fragments)
    {
        int wid = t >> 5;
        wmma::fragment<wmma::accumulator, 16, 16, 16, float> acc[8];
#pragma unroll
        for (int c = 0; c < 8; c++) wmma::fill_fragment(acc[c], 0.f);

#pragma unroll
        for (int k = 0; k < 8; k++) {
            wmma::fragment<wmma::matrix_a, 16, 16, 16, __half, wmma::row_major> af;
            wmma::load_matrix_sync(af, Xh + (wid * 16) * LDH + k * 16, LDH);
#pragma unroll
            for (int c = 0; c < 8; c++) {
                wmma::fragment<wmma::matrix_b, 16, 16, 16, __half, wmma::row_major> bf;
                wmma::load_matrix_sync(bf, Wh + (k * 16) * LDH + c * 16, LDH);
                wmma::mma_sync(acc[c], af, bf, acc[c]);
            }
        }
        __syncthreads();   // all warps done reading Xh/Wh before aliasing as Cs
#pragma unroll
        for (int c = 0; c < 8; c++)
            wmma::store_matrix_sync(Cs + (wid * 16) * LDH + c * 16,
                                    acc[c], LDH, wmma::mem_row_major);
    }
    __syncthreads();

    // epilogue: h1h store + attention logits (16 rows per thread)
    const int c0 = (t & 31) * 4;
    const int r0 = (t >> 5) * 16;
    const int head = c0 >> 5;
#pragma unroll
    for (int r = 0; r < 16; r++) {
        int rr = r0 + r;
        int row = row0 + rr;
        if (row < n) {
            float4 v = *(const float4*)&Cs[rr * LDH + c0];
            __half2 p0 = __floats2half2_rn(v.x, v.y);
            __half2 p1 = __floats2half2_rn(v.z, v.w);
            uint2 pk;
            pk.x = *(unsigned int*)&p0;
            pk.y = *(unsigned int*)&p1;
            *(uint2*)&g_h1h[(size_t)row * 64 + (c0 >> 1)] = pk;
            float ps = v.x * s_as[c0]     + v.y * s_as[c0 + 1]
                     + v.z * s_as[c0 + 2] + v.w * s_as[c0 + 3];
            float pd = v.x * s_ad[c0]     + v.y * s_ad[c0 + 1]
                     + v.z * s_ad[c0 + 2] + v.w * s_ad[c0 + 3];
            atomicAdd(&s_als[rr][head], ps);
            atomicAdd(&s_ald[rr][head], pd);
        }
    }
    __syncthreads();
    for (int i = t; i < GM_ROWS * 4; i += 256) {
        int r = i >> 2, hh = i & 3;
        int row = row0 + r;
        if (row < n) {
            g_als1[row * 4 + hh] = s_als[r][hh];
            g_ald1[row * 4 + hh] = s_ald[r][hh];
        }
    }
}

// ---------------- k_agg1: CSR warp-per-node aggregate (no atomics) -----------
__global__ void __launch_bounds__(256)
k_agg1(const float* __restrict__ b1, int N) {
    int node = (blockIdx.x * blockDim.x + threadIdx.x) >> 5;
    if (node >= N) return;
    int lane = threadIdx.x & 31;
    int h = lane >> 3;
    float ald = __ldg(&g_ald1[node * 4 + h]);
    int j   = g_rowptr[node];
    int end = j + g_deg[node];
    float4 acc = make_float4(0.f, 0.f, 0.f, 0.f);
    float den = 0.f;

    for (; j + 1 < end; j += 2) {
        int s0 = __ldg(&g_csrc[j]);
        int s1 = __ldg(&g_csrc[j + 1]);
        float w0 = lexp(__ldg(&g_als1[s0 * 4 + h]) + ald);
        float w1 = lexp(__ldg(&g_als1[s1 * 4 + h]) + ald);
        uint2 u0 = *(const uint2*)&g_h1h[(size_t)s0 * 64 + lane * 2];
        uint2 u1 = *(const uint2*)&g_h1h[(size_t)s1 * 64 + lane * 2];
        float2 a0 = __half22float2(*(__half2*)&u0.x);
        float2 a1 = __half22float2(*(__half2*)&u0.y);
        float2 c0 = __half22float2(*(__half2*)&u1.x);
        float2 c1 = __half22float2(*(__half2*)&u1.y);
        acc.x += w0 * a0.x + w1 * c0.x;
        acc.y += w0 * a0.y + w1 * c0.y;
        acc.z += w0 * a1.x + w1 * c1.x;
        acc.w += w0 * a1.y + w1 * c1.y;
        den   += w0 + w1;
    }
    if (j < end) {
        int s0 = __ldg(&g_csrc[j]);
        float w0 = lexp(__ldg(&g_als1[s0 * 4 + h]) + ald);
        uint2 u0 = *(const uint2*)&g_h1h[(size_t)s0 * 64 + lane * 2];
        float2 a0 = __half22float2(*(__half2*)&u0.x);
        float2 a1 = __half22float2(*(__half2*)&u0.y);
        acc.x += w0 * a0.x; acc.y += w0 * a0.y;
        acc.z += w0 * a1.x; acc.w += w0 * a1.y;
        den += w0;
    }

    float inv = __fdividef(1.f, den);
    float4 bb = *(const float4*)&b1[lane * 4];
    float4 o;
    o.x = fmaxf(acc.x * inv + bb.x, 0.f);
    o.y = fmaxf(acc.y * inv + bb.y, 0.f);
    o.z = fmaxf(acc.z * inv + bb.z, 0.f);
    o.w = fmaxf(acc.w * inv + bb.w, 0.f);
    *(float4*)&g_x2[(size_t)node * 128 + lane * 4] = o;
}

// ---------------- k_layer2: x2 @ W2 + layer-2 logits -------------------------
__global__ void __launch_bounds__(128)
k_layer2(const float* __restrict__ W2,
         const float* __restrict__ a_src2, const float* __restrict__ a_dst2,
         int n) {
    __shared__ float W2s[128 * 16];
    __shared__ float xs[8][128];
    __shared__ float outs[8][16];
    __shared__ float sa2[16], sd2[16];

    int t = threadIdx.x;
    int row0 = blockIdx.x * 8;

    for (int i = t; i < 128 * 16 / 4; i += 128)
        ((float4*)W2s)[i] = ((const float4*)W2)[i];
    if (t < 16) { sa2[t] = a_src2[t]; sd2[t] = a_dst2[t]; }
    __syncthreads();

    int nl = t >> 4, seg = t & 15;
    int row = row0 + nl;
    {
        int c = seg * 8;
#pragma unroll
        for (int jj = 0; jj < 2; jj++) {
            float4 v = (row < n)
                ? *(const float4*)&g_x2[(size_t)row * 128 + c + 4 * jj]
                : make_float4(0.f, 0.f, 0.f, 0.f);
            *(float4*)&xs[nl][c + 4 * jj] = v;
        }
    }
    __syncthreads();

    int o = seg;
    float acc = 0.f;
#pragma unroll 8
    for (int k = 0; k < 128; k += 4) {
        float4 xv = *(const float4*)&xs[nl][k];
        acc += xv.x * W2s[(k + 0) * 16 + o] + xv.y * W2s[(k + 1) * 16 + o]
             + xv.z * W2s[(k + 2) * 16 + o] + xv.w * W2s[(k + 3) * 16 + o];
    }
    outs[nl][o] = acc;
    // pack channel pair (o even) -> fp16x2 via shfl from o+1 (same node, same warp)
    float accn = __shfl_down_sync(0xffffffffu, acc, 1);
    if (!(o & 1) && row < n)
        g_h2h[row * 8 + (o >> 1)] = __floats2half2_rn(acc, accn);
    __syncthreads();

    if (o == 0 && row < n) {
        float ss = 0.f, sd = 0.f;
#pragma unroll
        for (int jj = 0; jj < 16; jj++) {
            ss += outs[nl][jj] * sa2[jj];
            sd += outs[nl][jj] * sd2[jj];
        }
        g_als2[row] = ss;
        g_ald2[row] = sd;
    }
}

// ---------------- k_agg2: CSR 8-thread-per-node aggregate into d_out ---------
__global__ void __launch_bounds__(256)
k_agg2(float* __restrict__ out, const float* __restrict__ b2, int N) {
    int g = blockIdx.x * blockDim.x + threadIdx.x;
    int node = g >> 3;
    if (node >= N) return;
    int c = g & 7;                         // channel pair index
    float ald = __ldg(&g_ald2[node]);
    int j   = g_rowptr[node];
    int end = j + g_deg[node];
    float ax = 0.f, ay = 0.f, den = 0.f;

    for (; j + 1 < end; j += 2) {
        int s0 = __ldg(&g_csrc[j]);
        int s1 = __ldg(&g_csrc[j + 1]);
        float w0 = lexp(__ldg(&g_als2[s0]) + ald);
        float w1 = lexp(__ldg(&g_als2[s1]) + ald);
        float2 f0 = __half22float2(g_h2h[s0 * 8 + c]);
        float2 f1 = __half22float2(g_h2h[s1 * 8 + c]);
        ax += w0 * f0.x + w1 * f1.x;
        ay += w0 * f0.y + w1 * f1.y;
        den += w0 + w1;
    }
    if (j < end) {
        int s0 = __ldg(&g_csrc[j]);
        float w0 = lexp(__ldg(&g_als2[s0]) + ald);
        float2 f0 = __half22float2(g_h2h[s0 * 8 + c]);
        ax += w0 * f0.x;
        ay += w0 * f0.y;
        den += w0;
    }

    float inv = __fdividef(1.f, den);
    float2 ov;
    ov.x = ax * inv + __ldg(&b2[2 * c]);
    ov.y = ay * inv + __ldg(&b2[2 * c + 1]);
    *(float2*)&out[node * 16 + 2 * c] = ov;
}

// ---------------- launch ------------------------------------------------------
extern "C" void kernel_launch(void* const* d_in, const int* in_sizes, int n_in,
                              void* d_out, int out_size) {
    const float* x      = (const float*)d_in[0];
    const int*   ei     = (const int*)d_in[1];     // JAX x64 off -> int32
    const float* W1     = (const float*)d_in[2];
    const float* a_src1 = (const float*)d_in[3];
    const float* a_dst1 = (const float*)d_in[4];
    const float* b1     = (const float*)d_in[5];
    const float* W2     = (const float*)d_in[6];
    const float* a_src2 = (const float*)d_in[7];
    const float* a_dst2 = (const float*)d_in[8];
    const float* b2     = (const float*)d_in[9];
    float* out = (float*)d_out;

    int N  = in_sizes[0] / 128;
    int E  = in_sizes[1] / 2;
    int ET = E + N;

    static int init_done = 0;
    if (!init_done) {
        cudaFuncSetAttribute(k_gemm1h, cudaFuncAttributeMaxDynamicSharedMemorySize,
                             GSMEM);
        init_done = 1;
    }

    k_zero<<<(N + 255) / 256, 256>>>(N);
    k_hist<<<(ET + 255) / 256, 256>>>(ei, E, ET);
    k_offsets<<<(N + 255) / 256, 256>>>(N);
    k_scatter<<<(ET + 255) / 256, 256>>>(ei, E, ET);

    k_gemm1h<<<(N + GM_ROWS - 1) / GM_ROWS, 256, GSMEM>>>(x, W1, a_src1, a_dst1, N);

    k_agg1<<<(N * 32 + 255) / 256, 256>>>(b1, N);
    k_layer2<<<(N + 7) / 8, 128>>>(W2, a_src2, a_dst2, N);
    k_agg2<<<(N * 8 + 255) / 256, 256>>>(out, b2, N);
}